// round 6
// baseline (speedup 1.0000x reference)
#include <cuda_runtime.h>
#include <cstdint>

// Output layout (floats): concatenated mips L0(2048)..L7(16), each [6,H,W,3] row-major.
#define OFF1 75497472ull
#define OFF2 94371840ull
#define OFF3 99090432ull
#define OFF4 100270080ull
#define OFF5 100564992ull
#define OFF6 100638720ull
#define OFF7 100657152ull

// L7 cross-block handoff (2 vertically-adjacent blocks per L7 pixel).
// Counters self-reset -> graph-replay safe. Fixed combine order -> deterministic.
__device__ float g_partial[6 * 16 * 16 * 2 * 3];
__device__ int   g_count[6 * 16 * 16];

__device__ __forceinline__ void cp_async16(uint32_t smem_dst, const void* gmem_src) {
    asm volatile("cp.async.cg.shared.global [%0], [%1], 16;" :: "r"(smem_dst), "l"(gmem_src));
}
__device__ __forceinline__ void cp_commit() {
    asm volatile("cp.async.commit_group;" ::: "memory");
}
__device__ __forceinline__ void cp_wait1() {
    asm volatile("cp.async.wait_group 1;" ::: "memory");
}

// Block = 256 threads, tile = 128 wide x 64 tall base px. Grid (16,32,6).
// 8 stages of 8 rows each; cp.async double-buffered pipeline (depth 2).
// Per stage: copy L0 out of smem (LDS.128->STG.128), 1 L1 px/thread, L2 via smem.
// Tail L3..L6 block-local from s2 tile; L7 via 2-block scratch handoff.
__global__ void __launch_bounds__(256, 6) mip_kernel(const float* __restrict__ in,
                                                     float* __restrict__ out) {
    const int t = threadIdx.x;
    const int bx = blockIdx.x, by = blockIdx.y, f = blockIdx.z;

    __shared__ float4 stagebuf[2][768];     // 2 x 12KB: 8 rows x 96 f4
    __shared__ float l1t[4][64][3];         // per-stage L1 tile
    __shared__ float s2[16][32][3];
    __shared__ float s3[8][16][3];
    __shared__ float s4[4][8][3];
    __shared__ float s5[2][4][3];
    __shared__ float s6[2][3];

    const float4* in4 = reinterpret_cast<const float4*>(in);
    float4* out4 = reinterpret_cast<float4*>(out);

    const uint32_t sb0 = (uint32_t)__cvta_generic_to_shared(&stagebuf[0][0]);
    const uint32_t sb1 = (uint32_t)__cvta_generic_to_shared(&stagebuf[1][0]);

    // f4 offset of stage s row 0 within global tensor; row stride = 1536 f4.
    auto stage_base = [&](int s) -> size_t {
        return (((size_t)(f * 2048 + by * 64 + s * 8) * 2048 + (size_t)bx * 128) * 3) >> 2;
    };
    auto issue_stage = [&](int s, uint32_t sbase) {
        const size_t gb = stage_base(s);
        #pragma unroll
        for (int k = 0; k < 3; k++) {
            const int idx = k * 256 + t;           // 0..767
            const int r = idx / 96, c = idx % 96;
            cp_async16(sbase + (uint32_t)idx * 16, in4 + gb + (size_t)r * 1536 + c);
        }
    };

    // Prologue: stages 0 and 1 in flight.
    issue_stage(0, sb0);
    cp_commit();
    issue_stage(1, sb1);
    cp_commit();

    const int x1 = t & 63, r1 = t >> 6;     // L1 pixel owned per stage

    #pragma unroll 2
    for (int s = 0; s < 8; s++) {
        cp_wait1();                          // stage s landed (s+1 may be in flight)
        __syncthreads();

        const float4* buf = stagebuf[s & 1];
        const float*  buff = reinterpret_cast<const float*>(buf);

        // ---- L0 copy: smem -> global, coalesced ----
        const size_t gb = stage_base(s);
        #pragma unroll
        for (int k = 0; k < 3; k++) {
            const int idx = k * 256 + t;
            const int r = idx / 96, c = idx % 96;
            __stcs(out4 + gb + (size_t)r * 1536 + c, buf[idx]);
        }

        // ---- L1: one output pixel per thread ----
        const float* rowA = buff + (2 * r1) * 384 + x1 * 6;
        const float* rowB = rowA + 384;
        const float2 a0 = reinterpret_cast<const float2*>(rowA)[0];
        const float2 a1 = reinterpret_cast<const float2*>(rowA)[1];
        const float2 a2 = reinterpret_cast<const float2*>(rowA)[2];
        const float2 b0 = reinterpret_cast<const float2*>(rowB)[0];
        const float2 b1 = reinterpret_cast<const float2*>(rowB)[1];
        const float2 b2 = reinterpret_cast<const float2*>(rowB)[2];
        float v[3];
        v[0] = 0.25f * ((a0.x + a1.y) + (b0.x + b1.y));
        v[1] = 0.25f * ((a0.y + a2.x) + (b0.y + b2.x));
        v[2] = 0.25f * ((a1.x + a2.y) + (b1.x + b2.y));

        const int y1 = by * 32 + s * 4 + r1;
        const size_t o1 = OFF1 + ((size_t)(f * 1024 + y1) * 1024 + (size_t)(bx * 64 + x1)) * 3;
        __stcs(out + o1 + 0, v[0]);
        __stcs(out + o1 + 1, v[1]);
        __stcs(out + o1 + 2, v[2]);
        l1t[r1][x1][0] = v[0];
        l1t[r1][x1][1] = v[1];
        l1t[r1][x1][2] = v[2];
        __syncthreads();                     // l1t ready; stagebuf[s&1] fully consumed

        // ---- L2: 2 rows x 32 px per stage ----
        if (t < 64) {
            const int x2 = t & 31, r2 = t >> 5;
            const int y2 = by * 16 + s * 2 + r2;
            const size_t o2 = OFF2 + ((size_t)(f * 512 + y2) * 512 + (size_t)(bx * 32 + x2)) * 3;
            #pragma unroll
            for (int c = 0; c < 3; c++) {
                const float w = 0.25f * (l1t[2 * r2][2 * x2][c] + l1t[2 * r2][2 * x2 + 1][c] +
                                         l1t[2 * r2 + 1][2 * x2][c] + l1t[2 * r2 + 1][2 * x2 + 1][c]);
                __stcs(out + o2 + c, w);
                s2[s * 2 + r2][x2][c] = w;
            }
        }

        // ---- prefetch stage s+2 into the buffer just freed ----
        if (s + 2 < 8)
            issue_stage(s + 2, (s & 1) ? sb1 : sb0);
        cp_commit();                          // commit every iteration (may be empty)
    }
    __syncthreads();                          // s2 complete

    // ---- L3: 16x8 per block (face 256) ----
    if (t < 128) {
        const int x = t & 15, y = t >> 4;
        const size_t o = OFF3 + ((size_t)(f * 256 + by * 8 + y) * 256 + (size_t)(bx * 16 + x)) * 3;
        #pragma unroll
        for (int c = 0; c < 3; c++) {
            const float w = 0.25f * (s2[2 * y][2 * x][c] + s2[2 * y][2 * x + 1][c] +
                                     s2[2 * y + 1][2 * x][c] + s2[2 * y + 1][2 * x + 1][c]);
            __stcs(out + o + c, w);
            s3[y][x][c] = w;
        }
    }
    __syncthreads();

    // ---- L4: 8x4 per block (face 128) ----
    if (t < 32) {
        const int x = t & 7, y = t >> 3;
        const size_t o = OFF4 + ((size_t)(f * 128 + by * 4 + y) * 128 + (size_t)(bx * 8 + x)) * 3;
        #pragma unroll
        for (int c = 0; c < 3; c++) {
            const float w = 0.25f * (s3[2 * y][2 * x][c] + s3[2 * y][2 * x + 1][c] +
                                     s3[2 * y + 1][2 * x][c] + s3[2 * y + 1][2 * x + 1][c]);
            __stcs(out + o + c, w);
            s4[y][x][c] = w;
        }
    }
    __syncthreads();

    // ---- L5: 4x2 per block (face 64) ----
    if (t < 8) {
        const int x = t & 3, y = t >> 2;
        const size_t o = OFF5 + ((size_t)(f * 64 + by * 2 + y) * 64 + (size_t)(bx * 4 + x)) * 3;
        #pragma unroll
        for (int c = 0; c < 3; c++) {
            const float w = 0.25f * (s4[2 * y][2 * x][c] + s4[2 * y][2 * x + 1][c] +
                                     s4[2 * y + 1][2 * x][c] + s4[2 * y + 1][2 * x + 1][c]);
            __stcs(out + o + c, w);
            s5[y][x][c] = w;
        }
    }
    __syncthreads();

    // ---- L6: 2x1 per block (face 32) ----
    if (t < 2) {
        const int x = t;
        const size_t o = OFF6 + ((size_t)(f * 32 + by) * 32 + (size_t)(bx * 2 + x)) * 3;
        #pragma unroll
        for (int c = 0; c < 3; c++) {
            const float w = 0.25f * (s5[0][2 * x][c] + s5[0][2 * x + 1][c] +
                                     s5[1][2 * x][c] + s5[1][2 * x + 1][c]);
            __stcs(out + o + c, w);
            s6[x][c] = w;
        }
    }
    __syncthreads();

    // ---- L7: 2-block vertical combine (face 16) ----
    if (t == 0) {
        const int Y7 = by >> 1;
        const int idx = (f * 16 + Y7) * 16 + bx;
        float* slot = g_partial + ((size_t)idx * 2 + (by & 1)) * 3;
        #pragma unroll
        for (int c = 0; c < 3; c++)
            slot[c] = s6[0][c] + s6[1][c];
        __threadfence();
        const int old = atomicAdd(&g_count[idx], 1);
        if (old == 1) {
            __threadfence();
            const float* sp = g_partial + (size_t)idx * 2 * 3;
            const size_t o7 = OFF7 + ((size_t)(f * 16 + Y7) * 16 + bx) * 3;
            #pragma unroll
            for (int c = 0; c < 3; c++)
                out[o7 + c] = 0.25f * (sp[c] + sp[3 + c]);
            atomicExch(&g_count[idx], 0);
        }
    }
}

extern "C" void kernel_launch(void* const* d_in, const int* in_sizes, int n_in,
                              void* d_out, int out_size) {
    const float* base = (const float*)d_in[0];
    float* out = (float*)d_out;
    mip_kernel<<<dim3(16, 32, 6), 256>>>(base, out);
}

// round 7
// speedup vs baseline: 1.0263x; 1.0263x over previous
#include <cuda_runtime.h>
#include <cstdint>

// Output layout (floats): concatenated mips L0(2048)..L7(16), each [6,H,W,3] row-major.
#define OFF1 75497472ull
#define OFF2 94371840ull
#define OFF3 99090432ull
#define OFF4 100270080ull
#define OFF5 100564992ull
#define OFF6 100638720ull
#define OFF7 100657152ull

// L7 cross-block handoff: each L7 pixel = 2x2 block quadrant group.
// Counters self-reset -> graph-replay safe. Fixed combine order -> deterministic.
__device__ float g_partial[6 * 16 * 16 * 4 * 3];
__device__ int   g_count[6 * 16 * 16];

__device__ __forceinline__ void cp_async16(uint32_t smem_dst, const void* gmem_src) {
    asm volatile("cp.async.cg.shared.global [%0], [%1], 16;" :: "r"(smem_dst), "l"(gmem_src));
}
__device__ __forceinline__ void cp_commit() {
    asm volatile("cp.async.commit_group;" ::: "memory");
}
__device__ __forceinline__ void cp_wait1() {
    asm volatile("cp.async.wait_group 1;" ::: "memory");
}

// Block = 256 threads, tile = 64x64 base px. Grid (32,32,6) = 6144 blocks (~15us each
// at 6/SM residency -> halved ragged-tail vs 128x64 tiles).
// 4 stages of 16 rows; cp.async double-buffered (depth 2, 12KB/stage).
// Per stage: L0 copy (LDS.128->STG.128), 1 L1 px/thread, L2 via smem tile.
// Tail L3..L6 block-local; L7 via 4-block quadrant scratch handoff.
__global__ void __launch_bounds__(256, 6) mip_kernel(const float* __restrict__ in,
                                                     float* __restrict__ out) {
    const int t = threadIdx.x;
    const int bx = blockIdx.x, by = blockIdx.y, f = blockIdx.z;

    __shared__ float4 stagebuf[2][768];     // 2 x 12KB: 16 rows x 48 f4
    __shared__ float l1t[8][32][3];         // per-stage L1 tile
    __shared__ float s2[16][16][3];
    __shared__ float s3[8][8][3];
    __shared__ float s4[4][4][3];
    __shared__ float s5[2][2][3];

    const float4* in4 = reinterpret_cast<const float4*>(in);
    float4* out4 = reinterpret_cast<float4*>(out);

    const uint32_t sb0 = (uint32_t)__cvta_generic_to_shared(&stagebuf[0][0]);
    const uint32_t sb1 = (uint32_t)__cvta_generic_to_shared(&stagebuf[1][0]);

    // f4 offset of stage s row 0; global row stride = 1536 f4.
    auto stage_base = [&](int s) -> size_t {
        return (((size_t)(f * 2048 + by * 64 + s * 16) * 2048 + (size_t)bx * 64) * 3) >> 2;
    };
    auto issue_stage = [&](int s, uint32_t sbase) {
        const size_t gb = stage_base(s);
        #pragma unroll
        for (int k = 0; k < 3; k++) {
            const int idx = k * 256 + t;            // 0..767
            const int r = idx / 48, c = idx % 48;   // 16 rows x 48 f4
            cp_async16(sbase + (uint32_t)idx * 16, in4 + gb + (size_t)r * 1536 + c);
        }
    };

    issue_stage(0, sb0);
    cp_commit();
    issue_stage(1, sb1);
    cp_commit();

    const int x1 = t & 31, r1 = t >> 5;     // L1 px owned per stage (8 rows x 32 px)

    #pragma unroll
    for (int s = 0; s < 4; s++) {
        cp_wait1();                          // stage s landed (s+1 in flight)
        __syncthreads();

        const float4* buf = stagebuf[s & 1];
        const float*  buff = reinterpret_cast<const float*>(buf);

        // ---- L0 copy: smem -> global, coalesced ----
        const size_t gb = stage_base(s);
        #pragma unroll
        for (int k = 0; k < 3; k++) {
            const int idx = k * 256 + t;
            const int r = idx / 48, c = idx % 48;
            __stcs(out4 + gb + (size_t)r * 1536 + c, buf[idx]);
        }

        // ---- L1: one output pixel per thread ----
        const float* rowA = buff + (2 * r1) * 192 + x1 * 6;
        const float* rowB = rowA + 192;
        const float2 a0 = reinterpret_cast<const float2*>(rowA)[0];
        const float2 a1 = reinterpret_cast<const float2*>(rowA)[1];
        const float2 a2 = reinterpret_cast<const float2*>(rowA)[2];
        const float2 b0 = reinterpret_cast<const float2*>(rowB)[0];
        const float2 b1 = reinterpret_cast<const float2*>(rowB)[1];
        const float2 b2 = reinterpret_cast<const float2*>(rowB)[2];
        float v[3];
        v[0] = 0.25f * ((a0.x + a1.y) + (b0.x + b1.y));
        v[1] = 0.25f * ((a0.y + a2.x) + (b0.y + b2.x));
        v[2] = 0.25f * ((a1.x + a2.y) + (b1.x + b2.y));

        const int y1 = by * 32 + s * 8 + r1;
        const size_t o1 = OFF1 + ((size_t)(f * 1024 + y1) * 1024 + (size_t)(bx * 32 + x1)) * 3;
        __stcs(out + o1 + 0, v[0]);
        __stcs(out + o1 + 1, v[1]);
        __stcs(out + o1 + 2, v[2]);
        l1t[r1][x1][0] = v[0];
        l1t[r1][x1][1] = v[1];
        l1t[r1][x1][2] = v[2];
        __syncthreads();                     // l1t ready; stagebuf[s&1] consumed

        // ---- L2: 4 rows x 16 px per stage ----
        if (t < 64) {
            const int x2 = t & 15, r2 = t >> 4;
            const int y2 = by * 16 + s * 4 + r2;
            const size_t o2 = OFF2 + ((size_t)(f * 512 + y2) * 512 + (size_t)(bx * 16 + x2)) * 3;
            #pragma unroll
            for (int c = 0; c < 3; c++) {
                const float w = 0.25f * (l1t[2 * r2][2 * x2][c] + l1t[2 * r2][2 * x2 + 1][c] +
                                         l1t[2 * r2 + 1][2 * x2][c] + l1t[2 * r2 + 1][2 * x2 + 1][c]);
                __stcs(out + o2 + c, w);
                s2[s * 4 + r2][x2][c] = w;
            }
        }

        if (s + 2 < 4)
            issue_stage(s + 2, (s & 1) ? sb1 : sb0);
        cp_commit();
    }
    __syncthreads();                          // s2 complete (16x16)

    // ---- L3: 8x8 per block (face 256) ----
    if (t < 64) {
        const int x = t & 7, y = t >> 3;
        const size_t o = OFF3 + ((size_t)(f * 256 + by * 8 + y) * 256 + (size_t)(bx * 8 + x)) * 3;
        #pragma unroll
        for (int c = 0; c < 3; c++) {
            const float w = 0.25f * (s2[2 * y][2 * x][c] + s2[2 * y][2 * x + 1][c] +
                                     s2[2 * y + 1][2 * x][c] + s2[2 * y + 1][2 * x + 1][c]);
            __stcs(out + o + c, w);
            s3[y][x][c] = w;
        }
    }
    __syncthreads();

    // ---- L4: 4x4 per block (face 128) ----
    if (t < 16) {
        const int x = t & 3, y = t >> 2;
        const size_t o = OFF4 + ((size_t)(f * 128 + by * 4 + y) * 128 + (size_t)(bx * 4 + x)) * 3;
        #pragma unroll
        for (int c = 0; c < 3; c++) {
            const float w = 0.25f * (s3[2 * y][2 * x][c] + s3[2 * y][2 * x + 1][c] +
                                     s3[2 * y + 1][2 * x][c] + s3[2 * y + 1][2 * x + 1][c]);
            __stcs(out + o + c, w);
            s4[y][x][c] = w;
        }
    }
    __syncthreads();

    // ---- L5: 2x2 per block (face 64) ----
    if (t < 4) {
        const int x = t & 1, y = t >> 1;
        const size_t o = OFF5 + ((size_t)(f * 64 + by * 2 + y) * 64 + (size_t)(bx * 2 + x)) * 3;
        #pragma unroll
        for (int c = 0; c < 3; c++) {
            const float w = 0.25f * (s4[2 * y][2 * x][c] + s4[2 * y][2 * x + 1][c] +
                                     s4[2 * y + 1][2 * x][c] + s4[2 * y + 1][2 * x + 1][c]);
            __stcs(out + o + c, w);
            s5[y][x][c] = w;
        }
    }
    __syncthreads();

    // ---- L6: 1 px per block (face 32) + L7 quadrant handoff (face 16) ----
    if (t == 0) {
        float v6[3];
        const size_t o6 = OFF6 + ((size_t)(f * 32 + by) * 32 + bx) * 3;
        #pragma unroll
        for (int c = 0; c < 3; c++) {
            v6[c] = 0.25f * (s5[0][0][c] + s5[0][1][c] + s5[1][0][c] + s5[1][1][c]);
            __stcs(out + o6 + c, v6[c]);
        }

        const int X7 = bx >> 1, Y7 = by >> 1;
        const int q = (by & 1) * 2 + (bx & 1);
        const int idx = (f * 16 + Y7) * 16 + X7;
        float* slot = g_partial + ((size_t)idx * 4 + q) * 3;
        slot[0] = v6[0]; slot[1] = v6[1]; slot[2] = v6[2];
        __threadfence();
        const int old = atomicAdd(&g_count[idx], 1);
        if (old == 3) {                       // last arriver combines
            __threadfence();
            const float* sp = g_partial + (size_t)idx * 4 * 3;
            const size_t o7 = OFF7 + ((size_t)(f * 16 + Y7) * 16 + X7) * 3;
            #pragma unroll
            for (int c = 0; c < 3; c++)
                out[o7 + c] = 0.25f * ((sp[c] + sp[3 + c]) + (sp[6 + c] + sp[9 + c]));
            atomicExch(&g_count[idx], 0);     // reset for next graph replay
        }
    }
}

extern "C" void kernel_launch(void* const* d_in, const int* in_sizes, int n_in,
                              void* d_out, int out_size) {
    const float* base = (const float*)d_in[0];
    float* out = (float*)d_out;
    mip_kernel<<<dim3(32, 32, 6), 256>>>(base, out);
}